// round 8
// baseline (speedup 1.0000x reference)
#include <cuda_runtime.h>
#include <cuda_fp16.h>
#include <stdint.h>

// ---------------- problem constants ----------------
#define BB 32
#define SS 1024
#define DD 256
#define FF 256
#define TT 8192
#define KDIM 768
#define NT 12            // K tiles of 64
#define N_TILES 512      // 64-row M tiles per conv
#define N_GATHER 512     // gather units (512 rows each)
#define TOTAL_ITEMS 1536
#define PERSIST_CTAS 296 // 148 SMs x 2

// ---------------- scratch (device globals; no allocation allowed) ----------
__device__ __half g_xh[(size_t)BB * SS * DD];
__device__ __half g_h1h[(size_t)BB * SS * FF];
__device__ __half g_W1h[FF * KDIM];
__device__ __half g_W2h[FF * KDIM];
__device__ int g_cum[BB * SS];
__device__ int g_mellen[BB];
__device__ unsigned int g_work;
__device__ unsigned int g_flags[N_TILES];

// ---------------- small helpers ----------------------------------------------
__device__ __forceinline__ uint32_t smem_u32(const void* p) {
    uint32_t a;
    asm("{ .reg .u64 t; cvta.to.shared.u64 t, %1; cvt.u32.u64 %0, t; }" : "=r"(a) : "l"(p));
    return a;
}
__device__ __forceinline__ void ldsm4(uint32_t r[4], uint32_t addr) {
    asm volatile("ldmatrix.sync.aligned.m8n8.x4.shared.b16 {%0,%1,%2,%3}, [%4];"
                 : "=r"(r[0]), "=r"(r[1]), "=r"(r[2]), "=r"(r[3]) : "r"(addr));
}
__device__ __forceinline__ void mma16816(float c[4], const uint32_t a[4],
                                         uint32_t b0, uint32_t b1) {
    asm volatile(
        "mma.sync.aligned.m16n8k16.row.col.f32.f16.f16.f32 "
        "{%0,%1,%2,%3}, {%4,%5,%6,%7}, {%8,%9}, {%0,%1,%2,%3};"
        : "+f"(c[0]), "+f"(c[1]), "+f"(c[2]), "+f"(c[3])
        : "r"(a[0]), "r"(a[1]), "r"(a[2]), "r"(a[3]), "r"(b0), "r"(b1));
}
__device__ __forceinline__ void cp16(uint32_t dst, const void* src, uint32_t sz) {
    asm volatile("cp.async.cg.shared.global [%0], [%1], 16, %2;"
                 :: "r"(dst), "l"(src), "r"(sz) : "memory");
}
#define CP_COMMIT() asm volatile("cp.async.commit_group;" ::: "memory")
#define CP_WAIT0()  asm volatile("cp.async.wait_group 0;" ::: "memory")

__device__ __forceinline__ void wait_flag(const unsigned int* f) {
    unsigned int v;
    for (;;) {
        asm volatile("ld.acquire.gpu.u32 %0, [%1];" : "=r"(v) : "l"(f) : "memory");
        if (v) break;
        __nanosleep(64);
    }
}

// swizzled byte offset of 16B chunk (row, kb 0..7) inside a [rows x 128B] tile
__device__ __forceinline__ uint32_t chunk_off64(int row, int kb) {
    return (uint32_t)(row * 128 + ((kb ^ (row & 7)) << 4));
}

// ---------------- fused prep kernel ------------------------------------------
// blocks [0,32): per-batch cumsum (+dur/mel); block 0 also resets queue/flags
// blocks [32, 32+2048): x -> fp16 (4096 elems per block, vectorized)
// blocks [2080, 2144): conv1 weight transpose+round
// blocks [2144, 2208): conv2 weight transpose+round
#define PREP_X_BLOCKS   2048
#define PREP_W_BLOCKS   64
#define PREP_GRID       (32 + PREP_X_BLOCKS + 2 * PREP_W_BLOCKS)

__global__ __launch_bounds__(1024) void prep_kernel(
    const float* __restrict__ x, const int* __restrict__ dur,
    const float* __restrict__ w1, const float* __restrict__ w2,
    __half* __restrict__ xh, __half* __restrict__ wh1, __half* __restrict__ wh2,
    float* __restrict__ out_dur, float* __restrict__ out_mel,
    int write_dur, int write_mel)
{
    const int bid = blockIdx.x;
    const int tid = threadIdx.x;

    if (bid < 32) {
        if (bid == 0) {   // reset persistent-queue state every call (graph replay!)
            if (tid < N_TILES) g_flags[tid] = 0u;
            if (tid == N_TILES) g_work = 0u;
        }
        __shared__ int sdata[SS];
        int b = bid;
        int v = dur[b * SS + tid];
        sdata[tid] = v;
        __syncthreads();
        #pragma unroll
        for (int off = 1; off < SS; off <<= 1) {
            int add = (tid >= off) ? sdata[tid - off] : 0;
            __syncthreads();
            sdata[tid] += add;
            __syncthreads();
        }
        g_cum[b * SS + tid] = sdata[tid];
        if (tid == SS - 1) {
            int ml = min(sdata[tid], TT);
            g_mellen[b] = ml;
            if (write_mel) out_mel[b] = (float)ml;
        }
        if (write_dur) out_dur[b * SS + tid] = (float)v;
    } else if (bid < 32 + PREP_X_BLOCKS) {
        size_t i = (size_t)(bid - 32) * 4096 + tid * 4;
        float4 v = *(const float4*)(x + i);
        *(__half2*)(xh + i)     = __floats2half2_rn(v.x, v.y);
        *(__half2*)(xh + i + 2) = __floats2half2_rn(v.z, v.w);
    } else {
        const float* w  = (bid < 32 + PREP_X_BLOCKS + PREP_W_BLOCKS) ? w1 : w2;
        __half* wh      = (bid < 32 + PREP_X_BLOCKS + PREP_W_BLOCKS) ? wh1 : wh2;
        int lb = (bid < 32 + PREP_X_BLOCKS + PREP_W_BLOCKS)
                   ? (bid - 32 - PREP_X_BLOCKS) : (bid - 32 - PREP_X_BLOCKS - PREP_W_BLOCKS);
        int idx = lb * 1024 + tid;
        int n = idx >> 8;
        int i = idx & 255;
        #pragma unroll
        for (int tap = 0; tap < 3; ++tap) {
            float v = w[(size_t)n * KDIM + i * 3 + tap];
            wh[(size_t)n * KDIM + tap * 256 + i] = __float2half_rn(v);
        }
    }
}

// ---------------- gather work routine ----------------------------------------
__device__ __forceinline__ void gather_work(int gid, const float* __restrict__ x,
                                            float* __restrict__ out) {
    const int tid  = threadIdx.x;
    const int b    = gid >> 4;
    const int t0   = (gid & 15) << 9;
    const int* cum = g_cum + b * SS;
    const int ml   = g_mellen[b];
    const float4* xb = (const float4*)(x + (size_t)b * SS * DD);
    float4* ob = (float4*)(out + (size_t)b * TT * DD);
    const int rsub = tid >> 3;
    const int csub = tid & 7;
    for (int pass = 0; pass < 16; ++pass) {
        int t = t0 + pass * 32 + rsub;
        float4* orow = ob + (size_t)t * 64;
        if (t < ml) {
            int lo = 0, hi = SS;
            while (lo < hi) {
                int mid = (lo + hi) >> 1;
                if (cum[mid] > t) hi = mid; else lo = mid + 1;
            }
            int src = min(lo, SS - 1);
            const float4* xr = xb + (size_t)src * 64;
            #pragma unroll
            for (int c8 = 0; c8 < 8; ++c8)
                orow[c8 * 8 + csub] = xr[c8 * 8 + csub];
        } else {
            float4 z = make_float4(0.f, 0.f, 0.f, 0.f);
            #pragma unroll
            for (int c8 = 0; c8 < 8; ++c8)
                orow[c8 * 8 + csub] = z;
        }
    }
}

__global__ void gather_kernel(const float* __restrict__ x, float* __restrict__ out) {
    gather_work(blockIdx.x, x, out);
}

// ---------------- persistent fused kernel ------------------------------------
// 296 CTAs pull items from a global queue:
//   items [0,768):    2 conv1 tiles : 1 gather unit   (conv1 tiles 0..511, gather 0..255)
//   items [768,1536): 2 conv2 tiles : 1 gather unit   (conv2 tiles 0..511, gather 256..511)
// conv2 tile t spins on conv1 flags {t-1, t, t+1} (clamped to batch).
// GEMM: CTA 64(M) x 256(N), BK=64, 8 warps, warp tile 32x64, fp16 1-term.
// smem/stage: A 8K | B 32K = 40KB, double buffered = 80KB.
__global__ __launch_bounds__(256, 2) void fused_kernel(
    const float* __restrict__ b1, const float* __restrict__ g1, const float* __restrict__ be1,
    const float* __restrict__ b2, const float* __restrict__ g2, const float* __restrict__ be2,
    const float* __restrict__ lw, const float* __restrict__ lb,
    const unsigned char* __restrict__ mask,
    float* __restrict__ out_ld,
    const float* __restrict__ xg, float* __restrict__ outg)
{
    extern __shared__ char smem[];
    __shared__ unsigned int s_item;
    const uint32_t sb = smem_u32(smem);
    const int tid  = threadIdx.x;
    const int wid  = tid >> 5;
    const int lane = tid & 31;
    const int warp_m = wid & 1;
    const int warp_n = wid >> 1;
    const int g   = lane >> 2;
    const int tig = lane & 3;

    // per-thread constants (hoisted out of the work loop)
    const int rowA0 = tid >> 3, kbA0 = tid & 7;
    const int rowA1 = (tid + 256) >> 3, kbA1 = tid & 7;
    const uint32_t dstA0 = chunk_off64(rowA0, kbA0);
    const uint32_t dstA1 = chunk_off64(rowA1, kbA1);

    uint32_t aoff[2][4], boff[4][4];
    #pragma unroll
    for (int mt = 0; mt < 2; ++mt) {
        int row = warp_m * 32 + mt * 16 + (lane & 15);
        #pragma unroll
        for (int ks = 0; ks < 4; ++ks)
            aoff[mt][ks] = chunk_off64(row, ks * 2 + (lane >> 4));
    }
    #pragma unroll
    for (int jp = 0; jp < 4; ++jp) {
        int row = warp_n * 64 + jp * 16 + ((lane >> 4) << 3) + (lane & 7);
        #pragma unroll
        for (int ks = 0; ks < 4; ++ks)
            boff[jp][ks] = 8192u + chunk_off64(row, ks * 2 + ((lane >> 3) & 1));
    }

    for (;;) {
        if (tid == 0) s_item = atomicAdd(&g_work, 1u);
        __syncthreads();
        const unsigned int it = s_item;
        if (it >= TOTAL_ITEMS) return;

        // ---- decode item ----
        int mode, t = 0, gid = -1;
        {
            unsigned int j  = (it < 768u) ? it : it - 768u;
            unsigned int g3 = j / 3u, r = j % 3u;
            mode = (it < 768u) ? 1 : 2;
            if (r < 2u) t = (int)(g3 * 2u + r);
            else        gid = (int)g3 + ((mode == 2) ? 256 : 0);
        }

        if (gid >= 0) {
            gather_work(gid, xg, outg);
            __syncthreads();
            continue;
        }

        const int m0     = t * 64;
        const int batch  = m0 >> 10;
        const int s_base = m0 & (SS - 1);
        const int tb     = t & 15;

        if (mode == 2 && tid == 0) {
            wait_flag(&g_flags[t]);
            if (tb > 0)  wait_flag(&g_flags[t - 1]);
            if (tb < 15) wait_flag(&g_flags[t + 1]);
        }
        __syncthreads();

        const __half* A_g = (mode == 1) ? g_xh : g_h1h;
        const __half* W_g = (mode == 1) ? g_W1h : g_W2h;
        const __half* A_b = A_g + ((size_t)batch << 10) * DD;
        const float* bias  = (mode == 1) ? b1  : b2;
        const float* gamma = (mode == 1) ? g1  : g2;
        const float* beta  = (mode == 1) ? be1 : be2;

        float c[2][8][4];
        #pragma unroll
        for (int mt = 0; mt < 2; ++mt)
            #pragma unroll
            for (int nt = 0; nt < 8; ++nt)
                #pragma unroll
                for (int q = 0; q < 4; ++q) c[mt][nt][q] = 0.f;

        auto issue = [&](int kt, int buf) {
            const int tap = kt >> 2;
            const int i0  = (kt & 3) * 64;
            const uint32_t stb = sb + (uint32_t)buf * 40960u;
            {
                int sA = s_base + rowA0 + tap - 1;
                uint32_t szA = ((unsigned)sA < (unsigned)SS) ? 16u : 0u;
                int sAc = min(max(sA, 0), SS - 1);
                cp16(stb + dstA0, A_b + (size_t)sAc * DD + i0 + kbA0 * 8, szA);
            }
            {
                int sA = s_base + rowA1 + tap - 1;
                uint32_t szA = ((unsigned)sA < (unsigned)SS) ? 16u : 0u;
                int sAc = min(max(sA, 0), SS - 1);
                cp16(stb + dstA1, A_b + (size_t)sAc * DD + i0 + kbA1 * 8, szA);
            }
            #pragma unroll
            for (int j = 0; j < 8; ++j) {
                int id = tid + j * 256;
                int rowB = id >> 3, kbB = id & 7;
                size_t wg = (size_t)rowB * KDIM + kt * 64 + kbB * 8;
                cp16(stb + 8192u + chunk_off64(rowB, kbB), W_g + wg, 16u);
            }
        };

        issue(0, 0);
        CP_COMMIT();

        for (int kt = 0; kt < NT; ++kt) {
            CP_WAIT0();
            __syncthreads();
            if (kt + 1 < NT) issue(kt + 1, (kt + 1) & 1);
            CP_COMMIT();

            const uint32_t stb = sb + (uint32_t)(kt & 1) * 40960u;
            #pragma unroll
            for (int ks = 0; ks < 4; ++ks) {
                uint32_t ah[2][4];
                ldsm4(ah[0], stb + aoff[0][ks]);
                ldsm4(ah[1], stb + aoff[1][ks]);
                #pragma unroll
                for (int jp = 0; jp < 4; ++jp) {
                    uint32_t bh[4];
                    ldsm4(bh, stb + boff[jp][ks]);
                    const int nA = 2 * jp, nB = 2 * jp + 1;
                    mma16816(c[0][nA], ah[0], bh[0], bh[1]);
                    mma16816(c[1][nA], ah[1], bh[0], bh[1]);
                    mma16816(c[0][nB], ah[0], bh[2], bh[3]);
                    mma16816(c[1][nB], ah[1], bh[2], bh[3]);
                }
            }
        }

        // ---- fused epilogue: bias, relu, row-LN ----
        __syncthreads();
        float* red = (float*)smem;   // [0:256) sum, [256:512) sq, [512:768) dot

        float s_[2][2] = {{0.f, 0.f}, {0.f, 0.f}};
        float q_[2][2] = {{0.f, 0.f}, {0.f, 0.f}};
        #pragma unroll
        for (int nt = 0; nt < 8; ++nt) {
            const int col = warp_n * 64 + nt * 8 + tig * 2;
            const float2 bv = *(const float2*)(bias + col);
            #pragma unroll
            for (int mt = 0; mt < 2; ++mt) {
                float v0 = fmaxf(c[mt][nt][0] + bv.x, 0.f);
                float v1 = fmaxf(c[mt][nt][1] + bv.y, 0.f);
                float v2 = fmaxf(c[mt][nt][2] + bv.x, 0.f);
                float v3 = fmaxf(c[mt][nt][3] + bv.y, 0.f);
                c[mt][nt][0] = v0; c[mt][nt][1] = v1;
                c[mt][nt][2] = v2; c[mt][nt][3] = v3;
                s_[mt][0] += v0 + v1;           s_[mt][1] += v2 + v3;
                q_[mt][0] += v0 * v0 + v1 * v1; q_[mt][1] += v2 * v2 + v3 * v3;
            }
        }
        #pragma unroll
        for (int off = 1; off <= 2; off <<= 1) {
            #pragma unroll
            for (int mt = 0; mt < 2; ++mt)
                #pragma unroll
                for (int h = 0; h < 2; ++h) {
                    s_[mt][h] += __shfl_xor_sync(0xffffffffu, s_[mt][h], off);
                    q_[mt][h] += __shfl_xor_sync(0xffffffffu, q_[mt][h], off);
                }
        }
        if (tig == 0) {
            #pragma unroll
            for (int mt = 0; mt < 2; ++mt)
                #pragma unroll
                for (int h = 0; h < 2; ++h) {
                    int row = warp_m * 32 + mt * 16 + g + h * 8;
                    red[warp_n * 64 + row]       = s_[mt][h];
                    red[256 + warp_n * 64 + row] = q_[mt][h];
                }
        }
        __syncthreads();
        float mu_[2][2], rs_[2][2];
        #pragma unroll
        for (int mt = 0; mt < 2; ++mt)
            #pragma unroll
            for (int h = 0; h < 2; ++h) {
                int row = warp_m * 32 + mt * 16 + g + h * 8;
                float st = red[row] + red[64 + row] + red[128 + row] + red[192 + row];
                float qt = red[256 + row] + red[320 + row] + red[384 + row] + red[448 + row];
                float mu  = st * (1.f / 256.f);
                float var = fmaxf(qt * (1.f / 256.f) - mu * mu, 0.f);
                mu_[mt][h] = mu;
                rs_[mt][h] = rsqrtf(var + 1e-5f);
            }

        if (mode == 1) {
            #pragma unroll
            for (int nt = 0; nt < 8; ++nt) {
                const int col = warp_n * 64 + nt * 8 + tig * 2;
                const float2 gv = *(const float2*)(gamma + col);
                const float2 bt = *(const float2*)(beta + col);
                #pragma unroll
                for (int mt = 0; mt < 2; ++mt) {
                    #pragma unroll
                    for (int h = 0; h < 2; ++h) {
                        int row = warp_m * 32 + mt * 16 + g + h * 8;
                        float y0 = (c[mt][nt][2*h]   - mu_[mt][h]) * rs_[mt][h] * gv.x + bt.x;
                        float y1 = (c[mt][nt][2*h+1] - mu_[mt][h]) * rs_[mt][h] * gv.y + bt.y;
                        *(__half2*)(g_h1h + (size_t)(m0 + row) * FF + col) =
                            __halves2half2(__float2half_rn(y0), __float2half_rn(y1));
                    }
                }
            }
            __syncthreads();
            if (tid == 0) {
                __threadfence();
                atomicExch(&g_flags[t], 1u);
            }
        } else {
            float d_[2][2] = {{0.f, 0.f}, {0.f, 0.f}};
            #pragma unroll
            for (int nt = 0; nt < 8; ++nt) {
                const int col = warp_n * 64 + nt * 8 + tig * 2;
                const float2 gv = *(const float2*)(gamma + col);
                const float2 bt = *(const float2*)(beta + col);
                const float2 lv = *(const float2*)(lw + col);
                #pragma unroll
                for (int mt = 0; mt < 2; ++mt) {
                    #pragma unroll
                    for (int h = 0; h < 2; ++h) {
                        float y0 = (c[mt][nt][2*h]   - mu_[mt][h]) * rs_[mt][h] * gv.x + bt.x;
                        float y1 = (c[mt][nt][2*h+1] - mu_[mt][h]) * rs_[mt][h] * gv.y + bt.y;
                        d_[mt][h] = fmaf(y0, lv.x, fmaf(y1, lv.y, d_[mt][h]));
                    }
                }
            }
            #pragma unroll
            for (int off = 1; off <= 2; off <<= 1)
                #pragma unroll
                for (int mt = 0; mt < 2; ++mt)
                    #pragma unroll
                    for (int h = 0; h < 2; ++h)
                        d_[mt][h] += __shfl_xor_sync(0xffffffffu, d_[mt][h], off);
            if (tig == 0) {
                #pragma unroll
                for (int mt = 0; mt < 2; ++mt)
                    #pragma unroll
                    for (int h = 0; h < 2; ++h) {
                        int row = warp_m * 32 + mt * 16 + g + h * 8;
                        red[512 + warp_n * 64 + row] = d_[mt][h];
                    }
            }
            __syncthreads();
            if (tid < 64) {
                float dt = red[512 + tid] + red[576 + tid] + red[640 + tid] + red[704 + tid]
                         + lb[0];
                int m = m0 + tid;
                out_ld[m] = mask[m] ? 0.f : dt;
            }
        }
        __syncthreads();   // protect s_item + smem before next item
    }
}

// ---------------- launcher ---------------------------------------------------
extern "C" void kernel_launch(void* const* d_in, const int* in_sizes, int n_in,
                              void* d_out, int out_size) {
    const float*         x        = (const float*)d_in[0];
    const unsigned char* mask     = (const unsigned char*)d_in[1];
    const int*           duration = (const int*)d_in[2];

    int w = 3;
    if (n_in >= 14 && in_sizes[3] < 16) w = 4;
    const float* c1w = (const float*)d_in[w + 0];
    const float* c1b = (const float*)d_in[w + 1];
    const float* l1g = (const float*)d_in[w + 2];
    const float* l1b = (const float*)d_in[w + 3];
    const float* c2w = (const float*)d_in[w + 4];
    const float* c2b = (const float*)d_in[w + 5];
    const float* l2g = (const float*)d_in[w + 6];
    const float* l2b = (const float*)d_in[w + 7];
    const float* lw  = (const float*)d_in[w + 8];
    const float* lb  = (const float*)d_in[w + 9];

    float* out = (float*)d_out;
    const long long n_out = (long long)BB * TT * DD;
    const long long n_ld  = (long long)BB * SS;
    int has_ld  = (out_size >= n_out + n_ld);
    int has_dur = (out_size >= n_out + 2 * n_ld);
    int has_mel = (out_size >= n_out + 2 * n_ld + BB);
    float* out_ld  = out + n_out;
    float* out_dur = out_ld + n_ld;
    float* out_mel = out_dur + n_ld;

    void* p;
    cudaGetSymbolAddress(&p, g_xh);  __half* xh  = (__half*)p;
    cudaGetSymbolAddress(&p, g_W1h); __half* W1h = (__half*)p;
    cudaGetSymbolAddress(&p, g_W2h); __half* W2h = (__half*)p;

    if (has_ld) {
        prep_kernel<<<PREP_GRID, 1024>>>(x, duration, c1w, c2w, xh, W1h, W2h,
                                         out_dur, out_mel, has_dur, has_mel);

        cudaFuncSetAttribute(fused_kernel,
                             cudaFuncAttributeMaxDynamicSharedMemorySize, 81920);

        fused_kernel<<<PERSIST_CTAS, 256, 81920>>>(
            c1b, l1g, l1b, c2b, l2g, l2b, lw, lb, mask, out_ld, x, out);
    } else {
        prep_kernel<<<32, 1024>>>(x, duration, c1w, c2w, xh, W1h, W2h,
                                  out_dur, out_mel, has_dur, has_mel);
        gather_kernel<<<BB * 16, 256>>>(x, out);
    }
}